// round 17
// baseline (speedup 1.0000x reference)
#include <cuda_runtime.h>
#include <cuda_fp16.h>
#include <cstdint>

#define H       1024
#define BATCH   16384
#define BM      128
#define BN      128
#define BK      64                  // halves per k-stage (128B rows)
#define NT      (H / BK)            // 16
#define TILE_BYTES (BM * 128)       // 16KB
#define STG_BYTES  (2 * TILE_BYTES) // 32KB (A + B)
#define STAGES  3
#define SMEM_TOTAL (STAGES * STG_BYTES)   // 96KB -> 2 CTAs/SM
#define MTILES  (BATCH / BM)        // 128
#define NTILES  (H / BN)            // 8
#define TILES_PER_PHASE (MTILES * NTILES) // 1024

// queue layout
#define NCONV   MTILES              // 128 convert jobs
#define Q_TW    NCONV               // 128..135: transpose-W strips
#define Q_TU    (NCONV + 8)         // 136..143: transpose-U strips
#define Q_G1    (NCONV + 16)        // 144..1167: GEMM1 tiles
#define Q_G2    (Q_G1 + TILES_PER_PHASE)   // 1168..2191: GEMM2 tiles
#define Q_END   (Q_G2 + TILES_PER_PHASE)

// scratch (__device__ globals: allowed)
__device__ __half g_prevh[(size_t)BATCH * H];  // prev in fp16 (32MB)
__device__ __half g_th[(size_t)BATCH * H];     // t intermediate fp16 (32MB)
__device__ __half g_Wh[(size_t)H * H];         // Wur[:,H:2H]^T fp16
__device__ __half g_Uh[(size_t)H * H];         // U^T fp16
__device__ unsigned g_queue;
__device__ unsigned g_done[MTILES];            // GEMM1 completions per mb
__device__ unsigned g_conv[MTILES];            // convert done per mb
__device__ unsigned g_wdone;                   // W transpose strips done (8)
__device__ unsigned g_udone;                   // U transpose strips done (8)

static __device__ __forceinline__ uint32_t smem_u32(const void* p) {
    return (uint32_t)__cvta_generic_to_shared(p);
}
static __device__ __forceinline__ void cp16(uint32_t dst, const void* src) {
    asm volatile("cp.async.cg.shared.global [%0], [%1], 16;" :: "r"(dst), "l"(src));
}
#define CP_COMMIT() asm volatile("cp.async.commit_group;" ::: "memory")
#define CP_WAIT(n)  asm volatile("cp.async.wait_group %0;" :: "n"(n) : "memory")

static __device__ __forceinline__ void ldsm_x4(uint32_t* r, uint32_t a) {
    asm volatile("ldmatrix.sync.aligned.m8n8.x4.shared.b16 {%0,%1,%2,%3}, [%4];"
                 : "=r"(r[0]), "=r"(r[1]), "=r"(r[2]), "=r"(r[3]) : "r"(a));
}
static __device__ __forceinline__ void mma_f16(float* c, const uint32_t* a, const uint32_t* b) {
    asm volatile("mma.sync.aligned.m16n8k16.row.col.f32.f16.f16.f32 "
                 "{%0,%1,%2,%3}, {%4,%5,%6,%7}, {%8,%9}, {%0,%1,%2,%3};"
                 : "+f"(c[0]), "+f"(c[1]), "+f"(c[2]), "+f"(c[3])
                 : "r"(a[0]), "r"(a[1]), "r"(a[2]), "r"(a[3]), "r"(b[0]), "r"(b[1]));
}

// ---------------------------------------------------------------------------
// stage loader: A [128 x 64h] + B [128 x 64h] fp16, 128B rows, SW128 swizzle
// ---------------------------------------------------------------------------
static __device__ __forceinline__ void load_stage(uint32_t stageBase,
        const __half* __restrict__ Ag, int m0,
        const __half* __restrict__ Bg, int n0, int k0, int tid)
{
#pragma unroll
    for (int j = 0; j < 4; j++) {
        int idx = tid + j * 256;
        int r = idx >> 3, c = idx & 7;
        uint32_t off = (uint32_t)idx * 16;
        uint32_t sw = off ^ ((off >> 3) & 0x70);
        cp16(stageBase + sw, Ag + (size_t)(m0 + r) * H + k0 + c * 8);
    }
#pragma unroll
    for (int j = 0; j < 4; j++) {
        int idx = tid + j * 256;
        int r = idx >> 3, c = idx & 7;
        uint32_t off = (uint32_t)idx * 16;
        uint32_t sw = off ^ ((off >> 3) & 0x70);
        cp16(stageBase + TILE_BYTES + sw, Bg + (size_t)(n0 + r) * H + k0 + c * 8);
    }
}

// ---------------------------------------------------------------------------
// GEMM core: acc[4][4][4] += A[128x1024] @ B[1024x128]^T  (fp16 ops, f32 acc)
// 8 warps 2(M) x 4(N); warp tile 64x32; m16n8k16 HMMA fed by ldmatrix.x4.
// ---------------------------------------------------------------------------
static __device__ __forceinline__ void gemm_core(float acc[4][4][4],
        const __half* __restrict__ Ag, const __half* __restrict__ Bg,
        int m0, int n0, char* smem)
{
    const uint32_t sb = smem_u32(smem);
    const int tid  = threadIdx.x;
    const int lane = tid & 31;
    const int warp = tid >> 5;
    const int wr   = warp >> 2;   // 0..1 (M)
    const int wc   = warp & 3;    // 0..3 (N)

    const int a_r  = wr * 64 + (lane & 15);          // + mi*16
    const int a_cx = lane >> 4;
    const int arx  = a_r & 7;
    const int b_r  = wc * 32 + ((lane >> 4) << 3) + (lane & 7);   // + g*16
    const int b_cx = (lane >> 3) & 1;
    const int brx  = b_r & 7;

#pragma unroll
    for (int i = 0; i < 4; i++)
#pragma unroll
        for (int j = 0; j < 4; j++)
#pragma unroll
            for (int k = 0; k < 4; k++) acc[i][j][k] = 0.f;

    load_stage(sb, Ag, m0, Bg, n0, 0, tid);
    CP_COMMIT();
    load_stage(sb + STG_BYTES, Ag, m0, Bg, n0, BK, tid);
    CP_COMMIT();

    for (int i = 0; i < NT; ++i) {
        const int s = i % STAGES;
        if (i == NT - 1) CP_WAIT(0); else CP_WAIT(1);
        __syncthreads();

        const uint32_t Abase = sb + s * STG_BYTES;
        const uint32_t Bbase = Abase + TILE_BYTES;
#pragma unroll
        for (int ks = 0; ks < 4; ks++) {       // k16 steps within BK=64
            uint32_t af[4][4], bf[4][2];
#pragma unroll
            for (int mi = 0; mi < 4; mi++) {
                uint32_t addr = Abase + (uint32_t)(a_r + mi * 16) * 128
                              + (uint32_t)((((ks << 1) + a_cx) ^ arx) << 4);
                ldsm_x4(af[mi], addr);
            }
#pragma unroll
            for (int g = 0; g < 2; g++) {
                uint32_t tmp[4];
                uint32_t addr = Bbase + (uint32_t)(b_r + g * 16) * 128
                              + (uint32_t)((((ks << 1) + b_cx) ^ brx) << 4);
                ldsm_x4(tmp, addr);
                bf[2 * g][0] = tmp[0]; bf[2 * g][1] = tmp[1];
                bf[2 * g + 1][0] = tmp[2]; bf[2 * g + 1][1] = tmp[3];
            }
#pragma unroll
            for (int mi = 0; mi < 4; mi++)
#pragma unroll
                for (int ni = 0; ni < 4; ni++)
                    mma_f16(acc[mi][ni], af[mi], bf[ni]);
        }

        if (i + 2 < NT) {
            load_stage(sb + ((i + 2) % STAGES) * STG_BYTES,
                       Ag, m0, Bg, n0, (i + 2) * BK, tid);
            CP_COMMIT();
        }
    }
    __syncthreads();   // smem reuse safe for next tile
}

// ---------------------------------------------------------------------------
// init: zero queue state (1 block)
// ---------------------------------------------------------------------------
__global__ void ggru_init() {
    int t = threadIdx.x;
    if (t < MTILES) { g_done[t] = 0; g_conv[t] = 0; }
    if (t == 128) g_queue = 0;
    if (t == 129) g_wdone = 0;
    if (t == 130) g_udone = 0;
}

// ---------------------------------------------------------------------------
// Fused persistent kernel: queue = [convert | transposeW | transposeU | G1 | G2]
// ---------------------------------------------------------------------------
__global__ __launch_bounds__(256, 2) void ggru_fused(
    const float* __restrict__ prev, const float* __restrict__ inp,
    const float* __restrict__ mask, const float* __restrict__ Wur,
    const float* __restrict__ U, float* __restrict__ out)
{
    extern __shared__ __align__(1024) char smem[];
    __shared__ unsigned s_claim;

    const int tid  = threadIdx.x;
    const int lane = tid & 31, warp = tid >> 5;
    const int wr = warp >> 2, wc = warp & 3;

    for (;;) {
        if (tid == 0) s_claim = atomicAdd(&g_queue, 1u);
        __syncthreads();
        const unsigned c = s_claim;
        __syncthreads();
        if (c >= Q_END) return;

        if (c < NCONV) {
            // ---------- convert prev rows [mb*128, mb*128+128) -> fp16 -----
            const int m0 = (int)c * BM;
            for (int idx = tid; idx < BM * (H / 4); idx += 256) {
                int r = idx >> 8, c4 = idx & 255;           // H/4 = 256 float4/row
                float4 v = *reinterpret_cast<const float4*>(
                    prev + (size_t)(m0 + r) * H + c4 * 4);
                __half2 h0 = __floats2half2_rn(v.x, v.y);
                __half2 h1 = __floats2half2_rn(v.z, v.w);
                uint2 u;
                u.x = *reinterpret_cast<uint32_t*>(&h0);
                u.y = *reinterpret_cast<uint32_t*>(&h1);
                *reinterpret_cast<uint2*>(&g_prevh[(size_t)(m0 + r) * H + c4 * 4]) = u;
            }
            __threadfence();
            __syncthreads();
            if (tid == 0) atomicAdd(&g_conv[c], 1u);
        } else if (c < Q_G1) {
            // ---------- transpose one 128-col strip of W or U -> fp16 ------
            const int isU = (c >= Q_TU);
            const int strip = (int)(c - (isU ? Q_TU : Q_TW));
            const float* src = isU ? U : (Wur + H);
            const int lds = isU ? H : 2 * H;
            __half* dst = isU ? g_Uh : g_Wh;
            const int n0s = strip * 128;
            float* tw = reinterpret_cast<float*>(smem) + warp * (32 * 33);

            for (int t = warp; t < 128; t += 8) {     // 32 k-tiles x 4 n-tiles
                const int kb = (t >> 2) << 5;
                const int nb = n0s + ((t & 3) << 5);
#pragma unroll
                for (int j = 0; j < 32; j++)
                    tw[j * 33 + lane] = src[(size_t)(kb + j) * lds + nb + lane];
                __syncwarp();
#pragma unroll
                for (int j = 0; j < 32; j++)
                    dst[(size_t)(nb + j) * H + kb + lane] = __float2half(tw[lane * 33 + j]);
                __syncwarp();
            }
            __threadfence();
            __syncthreads();
            if (tid == 0) atomicAdd(isU ? &g_udone : &g_wdone, 1u);
        } else if (c < Q_G2) {
            // ---------------- GEMM1: t = s * sigmoid(prev@Wr + g) ----------
            const unsigned id = c - Q_G1;
            const int mb = (int)(id >> 3), nb = (int)(id & 7);
            const int m0 = mb * BM, n0 = nb * BN;

            if (tid == 0) {
                while (atomicAdd(&g_conv[mb], 0u) == 0u) __nanosleep(32);
                while (atomicAdd(&g_wdone, 0u) < 8u) __nanosleep(32);
            }
            __syncthreads();
            __threadfence();

            float acc[4][4][4];
            gemm_core(acc, g_prevh, g_Wh, m0, n0, smem);

#pragma unroll
            for (int mi = 0; mi < 4; mi++) {
#pragma unroll
                for (int ni = 0; ni < 4; ni++) {
                    const int r0 = m0 + wr * 64 + mi * 16 + (lane >> 2);
                    const int c0 = n0 + wc * 32 + ni * 8 + (lane & 3) * 2;
#pragma unroll
                    for (int j = 0; j < 2; j++) {
                        const int row = r0 + j * 8;
                        const float* irow = inp + (size_t)row * (3 * H);
                        float2 g = *reinterpret_cast<const float2*>(irow + 2 * H + c0);
                        float2 s = *reinterpret_cast<const float2*>(irow + c0);
                        float x0 = acc[mi][ni][j * 2 + 0] + g.x;
                        float x1 = acc[mi][ni][j * 2 + 1] + g.y;
                        float t0 = s.x * (1.f / (1.f + __expf(-x0)));
                        float t1 = s.y * (1.f / (1.f + __expf(-x1)));
                        __half2 hv = __floats2half2_rn(t0, t1);
                        *reinterpret_cast<uint32_t*>(&g_th[(size_t)row * H + c0]) =
                            *reinterpret_cast<uint32_t*>(&hv);
                    }
                }
            }
            __threadfence();
            __syncthreads();
            if (tid == 0) atomicAdd(&g_done[mb], 1u);
        } else {
            // ---------------- GEMM2: out = prev + m*(tanh(t@U + s)+1) ------
            const unsigned id = c - Q_G2;
            const int mb = (int)(id >> 3), nb = (int)(id & 7);
            const int m0 = mb * BM, n0 = nb * BN;

            if (tid == 0) {
                while (atomicAdd(&g_udone, 0u) < 8u) __nanosleep(32);
                while (atomicAdd(&g_done[mb], 0u) < (unsigned)NTILES) __nanosleep(64);
            }
            __syncthreads();
            __threadfence();

            float acc[4][4][4];
            gemm_core(acc, g_th, g_Uh, m0, n0, smem);

#pragma unroll
            for (int mi = 0; mi < 4; mi++) {
#pragma unroll
                for (int ni = 0; ni < 4; ni++) {
                    const int r0 = m0 + wr * 64 + mi * 16 + (lane >> 2);
                    const int c0 = n0 + wc * 32 + ni * 8 + (lane & 3) * 2;
#pragma unroll
                    for (int j = 0; j < 2; j++) {
                        const int row = r0 + j * 8;
                        float2 s  = *reinterpret_cast<const float2*>(inp + (size_t)row * (3 * H) + c0);
                        float2 pv = *reinterpret_cast<const float2*>(prev + (size_t)row * H + c0);
                        float mk = mask[row];
                        float n0v = tanhf(acc[mi][ni][j * 2 + 0] + s.x);
                        float n1v = tanhf(acc[mi][ni][j * 2 + 1] + s.y);
                        float2 o;
                        o.x = pv.x + mk * (n0v + 1.f);
                        o.y = pv.y + mk * (n1v + 1.f);
                        *reinterpret_cast<float2*>(out + (size_t)row * H + c0) = o;
                    }
                }
            }
        }
    }
}

// ---------------------------------------------------------------------------
extern "C" void kernel_launch(void* const* d_in, const int* in_sizes, int n_in,
                              void* d_out, int out_size) {
    const float* inp  = (const float*)d_in[0];   // [16384, 3072]
    const float* prev = (const float*)d_in[1];   // [16384, 1024]
    const float* mask = (const float*)d_in[2];   // [16384]
    const float* Wur  = (const float*)d_in[3];   // [1024, 2048]
    const float* U    = (const float*)d_in[4];   // [1024, 1024]
    float* out = (float*)d_out;                  // [16384, 1024]

    cudaFuncSetAttribute(ggru_fused, cudaFuncAttributeMaxDynamicSharedMemorySize, SMEM_TOTAL);

    ggru_init<<<1, 256>>>();
    ggru_fused<<<304, 256, SMEM_TOTAL>>>(prev, inp, mask, Wur, U, out);
}